// round 4
// baseline (speedup 1.0000x reference)
#include <cuda_runtime.h>
#include <cstddef>

#define BB 32
#define TT 512
#define DD 512
#define MAXLEN 2048
#define ROWS_PER_BLOCK 8

// scratch (device globals — no allocation allowed)
__device__ int g_csum[BB * TT];
__device__ int g_dursum[BB];

// Kernel 1: per-batch inclusive scan of duration; also writes mel_lengths tail.
__global__ void scan_kernel(const int* __restrict__ dur,
                            float* __restrict__ out, int tail) {
    __shared__ int s[TT];
    const int b = blockIdx.x;
    const int tid = threadIdx.x;
    s[tid] = dur[b * TT + tid];
    __syncthreads();
    // Hillis–Steele inclusive scan over 512 elements (9 steps)
    #pragma unroll
    for (int off = 1; off < TT; off <<= 1) {
        int add = (tid >= off) ? s[tid - off] : 0;
        __syncthreads();
        s[tid] += add;
        __syncthreads();
    }
    g_csum[b * TT + tid] = s[tid];
    if (tid == TT - 1) {
        int ds = s[tid];
        g_dursum[b] = ds;
        // mel_lengths = max(dur_sum, 1), stored as float in the concat tail
        out[tail + b] = (float)(ds > 0 ? ds : 1);
    }
}

// Kernel 2: each block = 8 output frames of one batch. Warp w owns frame
// t = blockIdx.x*8 + w: binary-search csum in smem (searchsorted right),
// then copy (or zero) one 512-float row as 128 float4.
__global__ void __launch_bounds__(256)
regulate_kernel(const float4* __restrict__ x, float4* __restrict__ out) {
    __shared__ int s_csum[TT];
    __shared__ int s_ds;
    const int b = blockIdx.y;
    const int tid = threadIdx.x;

    for (int i = tid; i < TT; i += 256) s_csum[i] = g_csum[b * TT + i];
    if (tid == 0) s_ds = g_dursum[b];
    __syncthreads();

    const int warp = tid >> 5;
    const int lane = tid & 31;
    const int t = blockIdx.x * ROWS_PER_BLOCK + warp;

    float4* orow = out + ((size_t)b * MAXLEN + t) * (DD / 4);

    if (t >= s_ds) {
        // zero padding (output buffer is poisoned, must write zeros)
        const float4 z = make_float4(0.f, 0.f, 0.f, 0.f);
        #pragma unroll
        for (int k = 0; k < 4; k++) orow[lane + 32 * k] = z;
    } else {
        // searchsorted right: first j with csum[j] > t
        int lo = 0, hi = TT;
        while (lo < hi) {
            int mid = (lo + hi) >> 1;
            if (s_csum[mid] > t) hi = mid; else lo = mid + 1;
        }
        int idx = lo < (TT - 1) ? lo : (TT - 1);  // clip (matches reference)
        const float4* xrow = x + ((size_t)b * TT + idx) * (DD / 4);
        #pragma unroll
        for (int k = 0; k < 4; k++) orow[lane + 32 * k] = xrow[lane + 32 * k];
    }
}

extern "C" void kernel_launch(void* const* d_in, const int* in_sizes, int n_in,
                              void* d_out, int out_size) {
    const float* x   = (const float*)d_in[0];   // [32,512,512] f32
    const int*   dur = (const int*)d_in[1];     // [32,512] i32
    float* out = (float*)d_out;                 // [32*2048*512 + 32] f32

    const int tail = out_size - BB;  // mel_lengths live at the end

    scan_kernel<<<BB, TT>>>(dur, out, tail);

    dim3 grid(MAXLEN / ROWS_PER_BLOCK, BB);
    regulate_kernel<<<grid, 256>>>((const float4*)x, (float4*)out);
}